// round 6
// baseline (speedup 1.0000x reference)
// R6: fp16 HMMA flash attention — BM=128, 8 warps/CTA (16 q-rows/warp),
// cp.async double-buffered KV, softmax interleaved with PV mmas.
#include <cuda_runtime.h>
#include <cuda_fp16.h>
#include <cstdint>
#include <cstddef>

#define NHEAD 16
#define SEQLEN 4096
#define HDIM 64
#define BM 128
#define BN 64
#define NT (SEQLEN / BN)
#define NTHREADS 256
#define LDH 72            // smem row stride in halfs -> conflict-free ldmatrix

// smem offsets in halfs
#define OFF_Q  0
#define OFF_K0 (BM * LDH)
#define OFF_V0 (OFF_K0 + BN * LDH)
#define OFF_K1 (OFF_V0 + BN * LDH)
#define OFF_V1 (OFF_K1 + BN * LDH)
#define SMEM_HALFS (OFF_V1 + BN * LDH)
#define SMEM_BYTES (SMEM_HALFS * 2)

// fp16 pre-converted copies (Q pre-scaled by 1/sqrt(D)*log2(e))
__device__ __half g_qh[(size_t)NHEAD * SEQLEN * HDIM];
__device__ __half g_kh[(size_t)NHEAD * SEQLEN * HDIM];
__device__ __half g_vh[(size_t)NHEAD * SEQLEN * HDIM];

__device__ __forceinline__ uint32_t smem_u32(const void* p) {
    uint32_t a;
    asm("{ .reg .u64 t; cvta.to.shared.u64 t, %1; cvt.u32.u64 %0, t; }" : "=r"(a) : "l"(p));
    return a;
}
__device__ __forceinline__ float ex2(float x) {
    float y; asm("ex2.approx.ftz.f32 %0, %1;" : "=f"(y) : "f"(x)); return y;
}
__device__ __forceinline__ uint32_t pack2(float a, float b) {
    __half2 h = __floats2half2_rn(a, b);
    return *reinterpret_cast<uint32_t*>(&h);
}
__device__ __forceinline__ void cpa16(uint32_t dst, const void* src) {
    asm volatile("cp.async.cg.shared.global [%0], [%1], 16;" :: "r"(dst), "l"(src));
}
__device__ __forceinline__ void cpa_commit() {
    asm volatile("cp.async.commit_group;");
}
template <int N>
__device__ __forceinline__ void cpa_wait() {
    asm volatile("cp.async.wait_group %0;" :: "n"(N));
}
__device__ __forceinline__ void ldmx4(uint32_t f[4], uint32_t addr) {
    asm volatile("ldmatrix.sync.aligned.m8n8.x4.shared.b16 {%0,%1,%2,%3}, [%4];"
                 : "=r"(f[0]), "=r"(f[1]), "=r"(f[2]), "=r"(f[3]) : "r"(addr));
}
__device__ __forceinline__ void ldmx4t(uint32_t f[4], uint32_t addr) {
    asm volatile("ldmatrix.sync.aligned.m8n8.x4.trans.shared.b16 {%0,%1,%2,%3}, [%4];"
                 : "=r"(f[0]), "=r"(f[1]), "=r"(f[2]), "=r"(f[3]) : "r"(addr));
}
__device__ __forceinline__ void mma16816(float d[4], const uint32_t a[4],
                                         uint32_t b0, uint32_t b1) {
    asm volatile(
        "mma.sync.aligned.m16n8k16.row.col.f32.f16.f16.f32 "
        "{%0,%1,%2,%3}, {%4,%5,%6,%7}, {%8,%9}, {%0,%1,%2,%3};"
        : "+f"(d[0]), "+f"(d[1]), "+f"(d[2]), "+f"(d[3])
        : "r"(a[0]), "r"(a[1]), "r"(a[2]), "r"(a[3]), "r"(b0), "r"(b1));
}

// ---------------- prepass: fp32 -> fp16 ----------------
__global__ void prep_f16(const float* __restrict__ q, const float* __restrict__ k,
                         const float* __restrict__ v) {
    const float qs = 0.125f * 1.44269504088896340736f;   // 1/sqrt(64)*log2(e)
    size_t i = ((size_t)blockIdx.x * blockDim.x + threadIdx.x) * 4;
    float4 a = *reinterpret_cast<const float4*>(q + i);
    *reinterpret_cast<uint2*>(&g_qh[i]) =
        make_uint2(pack2(a.x * qs, a.y * qs), pack2(a.z * qs, a.w * qs));
    float4 b = *reinterpret_cast<const float4*>(k + i);
    *reinterpret_cast<uint2*>(&g_kh[i]) = make_uint2(pack2(b.x, b.y), pack2(b.z, b.w));
    float4 c = *reinterpret_cast<const float4*>(v + i);
    *reinterpret_cast<uint2*>(&g_vh[i]) = make_uint2(pack2(c.x, c.y), pack2(c.z, c.w));
}

// ---------------- main kernel ----------------
__global__ void __launch_bounds__(NTHREADS, 2)
fa16x(float* __restrict__ out) {
    extern __shared__ __half sm[];
    const int tid  = threadIdx.x;
    const int w    = tid >> 5;
    const int lane = tid & 31;
    const int g    = lane >> 2;
    const int t    = lane & 3;
    const int h    = blockIdx.y;
    const int q0   = blockIdx.x * BM;

    const __half* qh = g_qh + (size_t)h * SEQLEN * HDIM;
    const __half* kh = g_kh + (size_t)h * SEQLEN * HDIM;
    const __half* vh = g_vh + (size_t)h * SEQLEN * HDIM;
    float*        oh = out  + (size_t)h * SEQLEN * HDIM;

    const uint32_t sbase = smem_u32(sm);
    const uint32_t kvb[2][2] = {
        { sbase + OFF_K0 * 2, sbase + OFF_V0 * 2 },
        { sbase + OFF_K1 * 2, sbase + OFF_V1 * 2 } };

    // cp.async coords: 256 threads, K/V tile = 64 rows x 128B = 512 chunks each
    const int cr = tid >> 3;            // row 0..31
    const int cc = (tid & 7) * 8;       // col in halfs
    const uint32_t cdst = (uint32_t)((cr * LDH + cc) * 2);

    // ---- prologue: KV(0) prefetch + Q load ----
    {
        #pragma unroll
        for (int j = 0; j < 2; j++) {
            cpa16(kvb[0][0] + cdst + j * 32 * LDH * 2, kh + (size_t)(cr + j * 32) * HDIM + cc);
            cpa16(kvb[0][1] + cdst + j * 32 * LDH * 2, vh + (size_t)(cr + j * 32) * HDIM + cc);
        }
        cpa_commit();
        #pragma unroll
        for (int i = 0; i < 4; i++) {
            int lin = (i * NTHREADS + tid) * 8;
            int r = lin >> 6, c = lin & 63;
            *reinterpret_cast<uint4*>(&sm[OFF_Q + r * LDH + c]) =
                *reinterpret_cast<const uint4*>(qh + (size_t)(q0 + r) * HDIM + c);
        }
    }
    cpa_wait<0>();
    __syncthreads();

    // ldmatrix lane addressing
    const int rl = (lane & 7) + ((lane >> 3) & 1) * 8;
    const int cl = ((lane >> 4) & 1) * 8;

    // Q fragments: 4 k-blocks, resident all kernel (warp owns rows w*16..w*16+15)
    const uint32_t qb = sbase + OFF_Q * 2;
    uint32_t qa[4][4];
    #pragma unroll
    for (int kk = 0; kk < 4; kk++)
        ldmx4(qa[kk], qb + (uint32_t)(((w * 16 + rl) * LDH + kk * 16 + cl) * 2));

    float o[8][4];
    #pragma unroll
    for (int i = 0; i < 8; i++) { o[i][0] = o[i][1] = o[i][2] = o[i][3] = 0.f; }
    float l0 = 0.f, l1 = 0.f;

    for (int kt = 0; kt < NT; kt++) {
        const int b = kt & 1;
        if (kt > 0) {
            cpa_wait<0>();
            __syncthreads();
        }
        if (kt + 1 < NT) {
            const __half* kp = kh + (size_t)(kt + 1) * BN * HDIM;
            const __half* vp = vh + (size_t)(kt + 1) * BN * HDIM;
            #pragma unroll
            for (int j = 0; j < 2; j++) {
                cpa16(kvb[1 - b][0] + cdst + j * 32 * LDH * 2,
                      kp + (size_t)(cr + j * 32) * HDIM + cc);
                cpa16(kvb[1 - b][1] + cdst + j * 32 * LDH * 2,
                      vp + (size_t)(cr + j * 32) * HDIM + cc);
            }
            cpa_commit();
        }

        const uint32_t kbc = kvb[b][0];
        const uint32_t vbc = kvb[b][1];

        // ---- S = Q K^T : 16 x 64 per warp ----
        float s[8][4];
        #pragma unroll
        for (int nb = 0; nb < 8; nb++)
            s[nb][0] = s[nb][1] = s[nb][2] = s[nb][3] = 0.f;
        #pragma unroll
        for (int kk = 0; kk < 4; kk++) {
            #pragma unroll
            for (int np = 0; np < 4; np++) {
                uint32_t f[4];
                ldmx4(f, kbc + (uint32_t)(((np * 16 + rl) * LDH + kk * 16 + cl) * 2));
                mma16816(s[2 * np],     qa[kk], f[0], f[2]);
                mma16816(s[2 * np + 1], qa[kk], f[1], f[3]);
            }
        }

        // ---- softmax + PV interleaved per kk-block ----
        // (MUFU ex2 bursts alternate with HMMA bursts -> dual-pipe issue)
        #pragma unroll
        for (int kk = 0; kk < 4; kk++) {
            float* sa = s[2 * kk];
            float* sb = s[2 * kk + 1];
            sa[0] = ex2(sa[0]); sa[1] = ex2(sa[1]);
            sa[2] = ex2(sa[2]); sa[3] = ex2(sa[3]);
            sb[0] = ex2(sb[0]); sb[1] = ex2(sb[1]);
            sb[2] = ex2(sb[2]); sb[3] = ex2(sb[3]);
            l0 += sa[0] + sa[1] + sb[0] + sb[1];
            l1 += sa[2] + sa[3] + sb[2] + sb[3];

            uint32_t pa[4];
            pa[0] = pack2(sa[0], sa[1]);
            pa[1] = pack2(sa[2], sa[3]);
            pa[2] = pack2(sb[0], sb[1]);
            pa[3] = pack2(sb[2], sb[3]);

            #pragma unroll
            for (int dp = 0; dp < 4; dp++) {
                uint32_t f[4];
                ldmx4t(f, vbc + (uint32_t)(((kk * 16 + rl) * LDH + dp * 16 + cl) * 2));
                mma16816(o[2 * dp],     pa, f[0], f[1]);
                mma16816(o[2 * dp + 1], pa, f[2], f[3]);
            }
        }
    }

    // ---- epilogue ----
    l0 += __shfl_xor_sync(0xffffffffu, l0, 1);
    l0 += __shfl_xor_sync(0xffffffffu, l0, 2);
    l1 += __shfl_xor_sync(0xffffffffu, l1, 1);
    l1 += __shfl_xor_sync(0xffffffffu, l1, 2);
    const float inv0 = 1.f / l0;
    const float inv1 = 1.f / l1;
    const int r0 = q0 + w * 16 + g;
    const int r1 = r0 + 8;
    #pragma unroll
    for (int dt = 0; dt < 8; dt++) {
        oh[(size_t)r0 * HDIM + dt * 8 + 2 * t]     = o[dt][0] * inv0;
        oh[(size_t)r0 * HDIM + dt * 8 + 2 * t + 1] = o[dt][1] * inv0;
        oh[(size_t)r1 * HDIM + dt * 8 + 2 * t]     = o[dt][2] * inv1;
        oh[(size_t)r1 * HDIM + dt * 8 + 2 * t + 1] = o[dt][3] * inv1;
    }
}

extern "C" void kernel_launch(void* const* d_in, const int* in_sizes, int n_in,
                              void* d_out, int out_size) {
    const float* q = (const float*)d_in[0];
    const float* k = (const float*)d_in[1];
    const float* v = (const float*)d_in[2];
    float* out = (float*)d_out;

    cudaFuncSetAttribute(fa16x, cudaFuncAttributeMaxDynamicSharedMemorySize, SMEM_BYTES);

    prep_f16<<<4096, 256>>>(q, k, v);
    dim3 grid(SEQLEN / BM, NHEAD);
    fa16x<<<grid, NTHREADS, SMEM_BYTES>>>(out);
}